// round 1
// baseline (speedup 1.0000x reference)
#include <cuda_runtime.h>
#include <math.h>

#define SEQL 512
#define BATCH 64
#define INF 512
#define HID 1024
#define OUTF 512

// Scratch: xi pre-projection and all hidden states (each 512*64*1024 fp32 = 134 MB)
__device__ float g_xi[(size_t)SEQL * BATCH * HID];
__device__ float g_hs[(size_t)SEQL * BATCH * HID];

// ---------------------------------------------------------------------------
// Classic 128x128 register-tiled fp32 GEMM: C[M,N] = A[M,K] @ B[K,N] + bias[N]
// Optional leaky-relu epilogue. M,N multiples of 128; K multiple of 8.
// ---------------------------------------------------------------------------
template <bool LEAKY>
__global__ __launch_bounds__(256) void sgemm_bias(
    const float* __restrict__ A, const float* __restrict__ B,
    const float* __restrict__ bias, float* __restrict__ C,
    int M, int N, int K)
{
    constexpr int BM = 128, BN = 128, BK = 8;
    __shared__ float As[BK][BM];
    __shared__ float Bs[BK][BN];

    const int tid = threadIdx.x;           // 256 threads
    const int bx = blockIdx.x;              // N tile
    const int by = blockIdx.y;              // M tile
    const int tx = tid & 15;                 // 0..15
    const int ty = tid >> 4;                 // 0..15

    float acc[8][8];
#pragma unroll
    for (int i = 0; i < 8; i++)
#pragma unroll
        for (int j = 0; j < 8; j++) acc[i][j] = 0.0f;

    const int aRow = tid >> 1;               // 0..127
    const int aCol = (tid & 1) * 4;          // 0 or 4
    const int bRow = tid >> 5;               // 0..7
    const int bCol = (tid & 31) * 4;         // 0..124

    const float* Ap = A + (size_t)(by * BM) * K;
    const float* Bp = B + (size_t)bx * BN;

    for (int k0 = 0; k0 < K; k0 += BK) {
        float4 av = *(const float4*)(Ap + (size_t)aRow * K + k0 + aCol);
        As[aCol + 0][aRow] = av.x;
        As[aCol + 1][aRow] = av.y;
        As[aCol + 2][aRow] = av.z;
        As[aCol + 3][aRow] = av.w;
        *(float4*)&Bs[bRow][bCol] =
            *(const float4*)(Bp + (size_t)(k0 + bRow) * N + bCol);
        __syncthreads();

#pragma unroll
        for (int kk = 0; kk < BK; kk++) {
            float a[8], b[8];
            *(float4*)&a[0] = *(const float4*)&As[kk][ty * 8];
            *(float4*)&a[4] = *(const float4*)&As[kk][ty * 8 + 4];
            *(float4*)&b[0] = *(const float4*)&Bs[kk][tx * 8];
            *(float4*)&b[4] = *(const float4*)&Bs[kk][tx * 8 + 4];
#pragma unroll
            for (int i = 0; i < 8; i++)
#pragma unroll
                for (int j = 0; j < 8; j++)
                    acc[i][j] += a[i] * b[j];
        }
        __syncthreads();
    }

    const int row0 = by * BM + ty * 8;
    const int col0 = bx * BN + tx * 8;
#pragma unroll
    for (int i = 0; i < 8; i++) {
#pragma unroll
        for (int j = 0; j < 8; j += 4) {
            float4 v;
            v.x = acc[i][j + 0] + bias[col0 + j + 0];
            v.y = acc[i][j + 1] + bias[col0 + j + 1];
            v.z = acc[i][j + 2] + bias[col0 + j + 2];
            v.w = acc[i][j + 3] + bias[col0 + j + 3];
            if (LEAKY) {
                v.x = v.x >= 0.f ? v.x : 0.01f * v.x;
                v.y = v.y >= 0.f ? v.y : 0.01f * v.y;
                v.z = v.z >= 0.f ? v.z : 0.01f * v.z;
                v.w = v.w >= 0.f ? v.w : 0.01f * v.w;
            }
            *(float4*)&C[(size_t)(row0 + i) * N + col0 + j] = v;
        }
    }
}

// ---------------------------------------------------------------------------
// One recurrence step: h_out = tanh(xi_t + h_in @ W)
// h_in/h_out: [64, 1024], W: [1024, 1024] (L2-resident across steps).
// Grid: (HID/32 col tiles, BATCH/16 row tiles) = (32, 4), 256 threads.
// Each thread computes 2 outputs (rows rg and rg+8 of its 16-row tile).
// ---------------------------------------------------------------------------
__global__ __launch_bounds__(256) void rnn_step(
    const float* __restrict__ h_in, float* __restrict__ h_out,
    const float* __restrict__ W, const float* __restrict__ xi_t)
{
    __shared__ float hA[16][32];
    __shared__ float sW[32][32];

    const int tid = threadIdx.x;
    const int c  = tid & 31;    // column within tile
    const int rg = tid >> 5;    // row group 0..7
    const int colBase = blockIdx.x * 32;
    const int rowBase = blockIdx.y * 16;

    float a0 = 0.0f, a1 = 0.0f;

    for (int k0 = 0; k0 < HID; k0 += 32) {
#pragma unroll
        for (int i = 0; i < 2; i++) {
            int e = tid + i * 256;
            int r = e >> 5, kk = e & 31;
            hA[r][kk] = h_in[(size_t)(rowBase + r) * HID + k0 + kk];
        }
#pragma unroll
        for (int i = 0; i < 4; i++) {
            int e = tid + i * 256;
            int kk = e >> 5, cc = e & 31;
            sW[kk][cc] = W[(size_t)(k0 + kk) * HID + colBase + cc];
        }
        __syncthreads();

#pragma unroll
        for (int kk = 0; kk < 32; kk++) {
            float w = sW[kk][c];
            a0 += hA[rg][kk] * w;
            a1 += hA[rg + 8][kk] * w;
        }
        __syncthreads();
    }

    const int col = colBase + c;
    const size_t i0 = (size_t)(rowBase + rg) * HID + col;
    const size_t i1 = (size_t)(rowBase + rg + 8) * HID + col;
    h_out[i0] = tanhf(xi_t[i0] + a0);
    h_out[i1] = tanhf(xi_t[i1] + a1);
}

// ---------------------------------------------------------------------------
extern "C" void kernel_launch(void* const* d_in, const int* in_sizes, int n_in,
                              void* d_out, int out_size)
{
    const float* x   = (const float*)d_in[0];  // [512, 64, 512]
    const float* h0  = (const float*)d_in[1];  // [64, 1024]
    const float* i_h = (const float*)d_in[2];  // [512, 1024]
    const float* h_h = (const float*)d_in[3];  // [1024, 1024]
    const float* h_o = (const float*)d_in[4];  // [1024, 512]
    const float* b_i = (const float*)d_in[5];  // [1024]
    const float* b_o = (const float*)d_in[6];  // [512]
    float* out = (float*)d_out;                // [512,64,512] outputs + [64,1024] h_final

    float* xi = nullptr;
    float* hs = nullptr;
    cudaGetSymbolAddress((void**)&xi, g_xi);
    cudaGetSymbolAddress((void**)&hs, g_hs);

    // 1) xi = x @ i_h + b_i   : [32768,512] @ [512,1024]
    {
        dim3 grid(HID / 128, (SEQL * BATCH) / 128);
        sgemm_bias<false><<<grid, 256>>>(x, i_h, b_i, xi, SEQL * BATCH, HID, INF);
    }

    // 2) scan: h_t = tanh(xi_t + h_{t-1} @ h_h), stored into hs[t]
    {
        dim3 grid(HID / 32, BATCH / 16);
        const float* hin = h0;
        for (int t = 0; t < SEQL; t++) {
            float* hout = hs + (size_t)t * BATCH * HID;
            rnn_step<<<grid, 256>>>(hin, hout, h_h, xi + (size_t)t * BATCH * HID);
            hin = hout;
        }
    }

    // 3) outputs = leaky_relu(hs @ h_o + b_o) : [32768,1024] @ [1024,512]
    {
        dim3 grid(OUTF / 128, (SEQL * BATCH) / 128);
        sgemm_bias<true><<<grid, 256>>>(hs, h_o, b_o, out, SEQL * BATCH, OUTF, HID);
    }

    // 4) h_final = hs[SEQL-1]
    cudaMemcpyAsync(out + (size_t)SEQL * BATCH * OUTF,
                    hs + (size_t)(SEQL - 1) * BATCH * HID,
                    (size_t)BATCH * HID * sizeof(float),
                    cudaMemcpyDeviceToDevice, 0);
}

// round 2
// speedup vs baseline: 1.9184x; 1.9184x over previous
#include <cuda_runtime.h>
#include <math.h>

#define SEQL 512
#define BATCH 64
#define INF 512
#define HID 1024
#define OUTF 512
#define NBLK 128
#define SCAN_THREADS 512

typedef unsigned long long u64;

// Scratch (device globals; allocation-free)
__device__ float g_xi [(size_t)SEQL * BATCH * HID];   // [t][b][c] row-major
__device__ float g_hsT[(size_t)SEQL * BATCH * HID];   // [t][c][r] transposed
__device__ float g_h0T[(size_t)BATCH * HID];          // [c][r]
__device__ unsigned g_count = 0;
__device__ unsigned g_phase = 0;

// ---------------- f32x2 helpers (packed fp32, 2x FMA throughput) -----------
__device__ __forceinline__ u64 pack2(float x, float y) {
    u64 d; asm("mov.b64 %0,{%1,%2};" : "=l"(d) : "f"(x), "f"(y)); return d;
}
__device__ __forceinline__ float2 unpack2(u64 d) {
    float2 v; asm("mov.b64 {%0,%1},%2;" : "=f"(v.x), "=f"(v.y) : "l"(d)); return v;
}
__device__ __forceinline__ u64 fma2(u64 a, u64 b, u64 c) {
    u64 d; asm("fma.rn.f32x2 %0,%1,%2,%3;" : "=l"(d) : "l"(a), "l"(b), "l"(c)); return d;
}
__device__ __forceinline__ u64 add2(u64 a, u64 b) {
    u64 d; asm("add.rn.f32x2 %0,%1,%2;" : "=l"(d) : "l"(a), "l"(b)); return d;
}

// ---------------------------------------------------------------------------
// Persistent scan kernel: h_t = tanh(xi_t + h_{t-1} @ W)
// 128 blocks x 512 threads; block b owns output cols [8b, 8b+8).
// W slice (1024x8) lives in SMEM as duplicated f32x2 pairs (64KB).
// h read transposed from global: hin[k*64 + r]  (k = hid index, r = batch).
// 16 warps: k split 8 ways (128 k each), rows split 2 ways (32 each).
// Lane tile: 4 rows (1 LDG.128) x 2 cols -> 4 FMA2 per k.
// Cross-warp reduction over the 8 k-splits via SMEM, then tanh + store.
// Grid-wide phase barrier between steps (all 128 blocks resident).
// ---------------------------------------------------------------------------
__global__ void __launch_bounds__(SCAN_THREADS, 1) rnn_scan(
    const float* __restrict__ h0T, const float* __restrict__ W,
    const float* __restrict__ xi, float* __restrict__ hsT)
{
    extern __shared__ u64 smdyn[];
    u64* wS2  = smdyn;           // [1024][8] dup pairs = 64KB
    u64* sRed = smdyn + 8192;    // [8 ksplit][8 col][32 rowpair] = 16KB

    const int tid = threadIdx.x;
    const int cb  = blockIdx.x * 8;

    // Load W column slice once, duplicated into f32x2 pairs
    for (int i = tid; i < 8192; i += SCAN_THREADS) {
        int k = i >> 3, c = i & 7;
        float w = W[(size_t)k * HID + cb + c];
        wS2[i] = pack2(w, w);
    }
    __syncthreads();

    const int wg   = tid >> 5, l = tid & 31;
    const int q    = wg >> 1;          // k-split 0..7
    const int half = wg & 1;           // row half 0..1
    const int qd   = l & 7;            // row quad within half
    const int cg   = l >> 3;           // col pair 0..3
    const int rowoff = half * 32 + qd * 4;
    const int kbeg = q * 128;

    for (int t = 0; t < SEQL; ++t) {
        const float* hin = t ? hsT + (size_t)(t - 1) * BATCH * HID : h0T;

        u64 a0 = 0, a1 = 0, a2 = 0, a3 = 0;
        const float* hp = hin + (size_t)kbeg * 64 + rowoff;
        const u64*   wp = wS2 + (size_t)kbeg * 8 + 2 * cg;
#pragma unroll 8
        for (int k = 0; k < 128; ++k) {
            ulonglong2 hv = *(const ulonglong2*)(hp + (size_t)k * 64);
            ulonglong2 wv = *(const ulonglong2*)(wp + (size_t)k * 8);
            a0 = fma2(hv.x, wv.x, a0);
            a1 = fma2(hv.y, wv.x, a1);
            a2 = fma2(hv.x, wv.y, a2);
            a3 = fma2(hv.y, wv.y, a3);
        }

        // partial store: sRed[q][c][rowpair]
        {
            int rp = half * 16 + qd * 2;
            sRed[((size_t)q * 8 + 2 * cg)     * 32 + rp    ] = a0;
            sRed[((size_t)q * 8 + 2 * cg)     * 32 + rp + 1] = a1;
            sRed[((size_t)q * 8 + 2 * cg + 1) * 32 + rp    ] = a2;
            sRed[((size_t)q * 8 + 2 * cg + 1) * 32 + rp + 1] = a3;
        }
        __syncthreads();

        if (tid < 256) {
            int rp2 = tid & 31;        // rowpair -> rows 2rp2, 2rp2+1
            int c   = tid >> 5;        // local col 0..7
            u64 s = sRed[(size_t)c * 32 + rp2];
#pragma unroll
            for (int qq = 1; qq < 8; ++qq)
                s = add2(s, sRed[((size_t)qq * 8 + c) * 32 + rp2]);
            float2 f = unpack2(s);
            const float* xit = xi + (size_t)t * BATCH * HID;
            float v0 = tanhf(f.x + xit[(size_t)(2 * rp2)     * HID + cb + c]);
            float v1 = tanhf(f.y + xit[(size_t)(2 * rp2 + 1) * HID + cb + c]);
            *(u64*)(hsT + (size_t)t * BATCH * HID + (size_t)(cb + c) * 64 + 2 * rp2)
                = pack2(v0, v1);
        }

        // ---- grid barrier ----
        __syncthreads();
        if (tid == 0) {
            __threadfence();
            unsigned ph;
            asm volatile("ld.acquire.gpu.u32 %0,[%1];" : "=r"(ph) : "l"(&g_phase) : "memory");
            unsigned arrived = atomicAdd(&g_count, 1u);
            if (arrived == NBLK - 1) {
                g_count = 0;
                __threadfence();
                atomicExch(&g_phase, ph + 1);
            } else {
                unsigned cur;
                do {
                    __nanosleep(32);
                    asm volatile("ld.acquire.gpu.u32 %0,[%1];" : "=r"(cur) : "l"(&g_phase) : "memory");
                } while (cur == ph);
            }
        }
        __syncthreads();
    }
}

// ---------------------------------------------------------------------------
// 128x128x8 f32x2 GEMM: C = A @ B + bias, optional leaky-relu.
// ATRANS: A is stored as [M/64][K][64] (the transposed hidden-state history).
// ---------------------------------------------------------------------------
template <bool ATRANS, bool LEAKY>
__global__ __launch_bounds__(256) void sgemm_f2(
    const float* __restrict__ A, const float* __restrict__ B,
    const float* __restrict__ bias, float* __restrict__ C,
    int M, int N, int K)
{
    constexpr int BM = 128, BN = 128, BK = 8;
    __shared__ __align__(16) float As[BK][BM];
    __shared__ __align__(16) float Bs[BK][BN];

    const int tid = threadIdx.x;
    const int bx = blockIdx.x, by = blockIdx.y;
    const int tx = tid & 15, ty = tid >> 4;

    u64 acc[8][4];
#pragma unroll
    for (int i = 0; i < 8; i++)
#pragma unroll
        for (int j = 0; j < 4; j++) acc[i][j] = 0ull;

    const int aRow = tid >> 1, aCol = (tid & 1) * 4;
    const int at_t = tid >> 7, at_kk = (tid >> 4) & 7, at_b = (tid & 15) * 4;
    const int bRow = tid >> 5, bCol = (tid & 31) * 4;

    for (int k0 = 0; k0 < K; k0 += BK) {
        if (!ATRANS) {
            float4 av = *(const float4*)(A + (size_t)(by * BM + aRow) * K + k0 + aCol);
            As[aCol + 0][aRow] = av.x;
            As[aCol + 1][aRow] = av.y;
            As[aCol + 2][aRow] = av.z;
            As[aCol + 3][aRow] = av.w;
        } else {
            float4 av = *(const float4*)(A + ((size_t)(by * 2 + at_t) * K + (k0 + at_kk)) * 64 + at_b);
            *(float4*)&As[at_kk][at_t * 64 + at_b] = av;
        }
        *(float4*)&Bs[bRow][bCol] =
            *(const float4*)(B + (size_t)(k0 + bRow) * N + bx * BN + bCol);
        __syncthreads();

#pragma unroll
        for (int kk = 0; kk < BK; kk++) {
            float4 alo = *(const float4*)&As[kk][ty * 8];
            float4 ahi = *(const float4*)&As[kk][ty * 8 + 4];
            ulonglong2 b01 = *(const ulonglong2*)&Bs[kk][tx * 8];
            ulonglong2 b23 = *(const ulonglong2*)&Bs[kk][tx * 8 + 4];
            float a[8] = {alo.x, alo.y, alo.z, alo.w, ahi.x, ahi.y, ahi.z, ahi.w};
#pragma unroll
            for (int i = 0; i < 8; i++) {
                u64 ad = pack2(a[i], a[i]);
                acc[i][0] = fma2(ad, b01.x, acc[i][0]);
                acc[i][1] = fma2(ad, b01.y, acc[i][1]);
                acc[i][2] = fma2(ad, b23.x, acc[i][2]);
                acc[i][3] = fma2(ad, b23.y, acc[i][3]);
            }
        }
        __syncthreads();
    }

    const int row0 = by * BM + ty * 8, col0 = bx * BN + tx * 8;
#pragma unroll
    for (int i = 0; i < 8; i++) {
        float out[8];
#pragma unroll
        for (int j = 0; j < 4; j++) {
            float2 f = unpack2(acc[i][j]);
            out[2 * j] = f.x; out[2 * j + 1] = f.y;
        }
#pragma unroll
        for (int j = 0; j < 8; j++) {
            float v = out[j] + bias[col0 + j];
            if (LEAKY) v = v >= 0.f ? v : 0.01f * v;
            out[j] = v;
        }
        *(float4*)&C[(size_t)(row0 + i) * N + col0]     = make_float4(out[0], out[1], out[2], out[3]);
        *(float4*)&C[(size_t)(row0 + i) * N + col0 + 4] = make_float4(out[4], out[5], out[6], out[7]);
    }
}

// ---------------------------------------------------------------------------
__global__ void transpose_h0(const float* __restrict__ in, float* __restrict__ out) {
    int i = blockIdx.x * 256 + threadIdx.x;        // 65536
    int c = i >> 6, r = i & 63;
    out[i] = in[(size_t)r * HID + c];              // out[c][r]
}
__global__ void transpose_hfinal(const float* __restrict__ hsTlast, float* __restrict__ out) {
    int i = blockIdx.x * 256 + threadIdx.x;        // 65536
    int r = i >> 10, c = i & 1023;
    out[i] = hsTlast[(size_t)c * 64 + r];          // out[r][c]
}

// ---------------------------------------------------------------------------
extern "C" void kernel_launch(void* const* d_in, const int* in_sizes, int n_in,
                              void* d_out, int out_size)
{
    const float* x   = (const float*)d_in[0];
    const float* h0  = (const float*)d_in[1];
    const float* i_h = (const float*)d_in[2];
    const float* h_h = (const float*)d_in[3];
    const float* h_o = (const float*)d_in[4];
    const float* b_i = (const float*)d_in[5];
    const float* b_o = (const float*)d_in[6];
    float* out = (float*)d_out;

    float *xi = nullptr, *hsT = nullptr, *h0T = nullptr;
    cudaGetSymbolAddress((void**)&xi,  g_xi);
    cudaGetSymbolAddress((void**)&hsT, g_hsT);
    cudaGetSymbolAddress((void**)&h0T, g_h0T);

    static int smem_set = 0;
    if (!smem_set) {
        cudaFuncSetAttribute(rnn_scan, cudaFuncAttributeMaxDynamicSharedMemorySize, 81920);
        smem_set = 1;
    }

    // 0) transpose h0 -> [c][r]
    transpose_h0<<<256, 256>>>(h0, h0T);

    // 1) xi = x @ i_h + b_i : [32768,512]@[512,1024]
    {
        dim3 grid(HID / 128, (SEQL * BATCH) / 128);
        sgemm_f2<false, false><<<grid, 256>>>(x, i_h, b_i, xi, SEQL * BATCH, HID, INF);
    }

    // 2) persistent scan (all 512 steps in one launch)
    rnn_scan<<<NBLK, SCAN_THREADS, 81920>>>(h0T, h_h, xi, hsT);

    // 3) outputs = leaky_relu(hsT @ h_o + b_o) : [32768,1024]@[1024,512]
    {
        dim3 grid(OUTF / 128, (SEQL * BATCH) / 128);
        sgemm_f2<true, true><<<grid, 256>>>(hsT, h_o, b_o, out, SEQL * BATCH, OUTF, HID);
    }

    // 4) h_final = transpose(hsT[511])
    transpose_hfinal<<<256, 256>>>(hsT + (size_t)(SEQL - 1) * BATCH * HID,
                                   out + (size_t)SEQL * BATCH * OUTF);
}